// round 1
// baseline (speedup 1.0000x reference)
#include <cuda_runtime.h>
#include <math.h>

// ---------------------------------------------------------------------------
// Actor_Critic fused pipeline, fp32 baseline.
//
// Algebraic reductions vs reference:
//  - gated_att = sigmoid(emb[idx] @ w_ta^T + b_ta) has only 4 distinct rows
//    (idx in [0,4)) -> precompute 4x256 table.
//  - lstm gates = [gated_fusion | gated_att] @ w_ih^T + b_ih + hx @ w_hh^T + b_hh.
//    The gated_att part (cols 256:512 of w_ih) + both biases depend only on idx
//    -> precompute pre2[4][1024]. Big GEMM becomes K=512 instead of K=768.
// ---------------------------------------------------------------------------

constexpr size_t S_B = 32768;

constexpr size_t O_TAB    = 0;                       // 4*256
constexpr size_t O_PRE2   = 1024;                    // 4*1024
constexpr size_t O_FUSION = 8192;                    // B*256
constexpr size_t O_GATES  = O_FUSION + S_B * 256;    // B*1024
constexpr size_t O_MLP    = O_GATES  + S_B * 1024;   // B*512
constexpr size_t O_QOUT   = O_MLP    + S_B * 512;    // B*256
constexpr size_t O_AVEC   = O_QOUT   + S_B * 256;    // B*256
constexpr size_t O_ATTNW  = O_AVEC   + S_B * 256;    // B*256
constexpr size_t O_POL1   = O_ATTNW  + S_B * 256;    // B*128
constexpr size_t O_POL2   = O_POL1   + S_B * 128;    // B*64
constexpr size_t O_VAL1   = O_POL2   + S_B * 64;     // B*64
constexpr size_t O_VAL2   = O_VAL1   + S_B * 64;     // B*32
constexpr size_t O_END    = O_VAL2   + S_B * 32;

__device__ float g_scratch[O_END];

__device__ __forceinline__ float sigmoidf_(float x) { return 1.f / (1.f + expf(-x)); }

// ---------------------------------------------------------------------------
// K0: build gated_att table (4x256) and pre2 table (4x1024). One block.
// ---------------------------------------------------------------------------
__global__ void k0_tables(const float* __restrict__ emb,  const float* __restrict__ w_ta,
                          const float* __restrict__ b_ta, const float* __restrict__ w_ih,
                          const float* __restrict__ b_ih, const float* __restrict__ b_hh,
                          float* __restrict__ tab, float* __restrict__ pre2) {
    int t = threadIdx.x;  // 1024 threads
    {
        int r = t >> 8, j = t & 255;
        float s = b_ta[j];
        #pragma unroll
        for (int k = 0; k < 25; k++) s += emb[r * 25 + k] * w_ta[j * 25 + k];
        tab[t] = sigmoidf_(s);
    }
    __syncthreads();  // makes tab's global writes visible within block
    {
        int j = t;  // 0..1023
        const float* wrow = &w_ih[(size_t)j * 512 + 256];
        float base = b_ih[j] + b_hh[j];
        for (int r = 0; r < 4; r++) {
            const float* tr = &tab[r * 256];
            float s = base;
            for (int k = 0; k < 256; k++) s += tr[k] * wrow[k];
            pre2[r * 1024 + j] = s;
        }
    }
}

// ---------------------------------------------------------------------------
// K1: gated_fusion = img_feat * tab[idx]
// ---------------------------------------------------------------------------
__global__ void k_fusion(const float* __restrict__ img, const int* __restrict__ idx,
                         const float* __restrict__ tab, float* __restrict__ out, int total) {
    int i = blockIdx.x * blockDim.x + threadIdx.x;
    if (i >= total) return;
    int b = i >> 8, j = i & 255;
    out[i] = img[i] * tab[idx[b] * 256 + j];
}

// ---------------------------------------------------------------------------
// K3: LSTM activation. gates [B,1024] (i,f,g,o) -> hx, cx
// ---------------------------------------------------------------------------
__global__ void k_lstm(const float* __restrict__ gates, const float* __restrict__ cx_in,
                       float* __restrict__ hx_out, float* __restrict__ cx_out, int total) {
    int i = blockIdx.x * blockDim.x + threadIdx.x;
    if (i >= total) return;
    int b = i >> 8, j = i & 255;
    const float* g = &gates[(size_t)b * 1024];
    float ig = sigmoidf_(g[j]);
    float fg = sigmoidf_(g[256 + j]);
    float gg = tanhf(g[512 + j]);
    float og = sigmoidf_(g[768 + j]);
    float c  = fg * cx_in[i] + ig * gg;
    float h  = og * tanhf(c);
    cx_out[i] = c;
    hx_out[i] = h;
}

// ---------------------------------------------------------------------------
// Generic tiled SGEMM:  C[M,N] = epi( sum_seg A_seg[M,Kseg] @ W_seg[N,Kseg]^T )
// A row-major with leading dim lda, W row-major [N, ldw] (PyTorch linear).
// EPI 0: + bias (if non-null), optional relu (ACT==1)
// EPI 1: + aux0[idxp[m]*1024 + n]          (gates + pre2 table)
// EPI 2: relu -> u = tanh(aux0[m*256+n] + v); out = u * aux1[m*512+256+n]
// ---------------------------------------------------------------------------
template <int BM, int BN, int BK, int TM, int TN, int ACT, int EPI>
__global__ void __launch_bounds__((BM / TM) * (BN / TN))
gemm_k(int M, int N,
       const float* __restrict__ A0, int lda0, const float* __restrict__ W0, int ldw0, int K0,
       const float* __restrict__ A1, int lda1, const float* __restrict__ W1, int ldw1, int K1,
       const float* __restrict__ bias, const float* __restrict__ aux0,
       const float* __restrict__ aux1, const int* __restrict__ idxp,
       float* __restrict__ C, int ldc) {
    constexpr int NT    = (BM / TM) * (BN / TN);
    constexpr int TCOLS = BN / TN;
    constexpr int BK4   = BK / 4;

    __shared__ float As[BK][BM + 4];
    __shared__ float Ws[BK][BN + 4];

    const int tid  = threadIdx.x;
    const int tcol = tid % TCOLS;
    const int trow = tid / TCOLS;
    const int m0   = blockIdx.y * BM;
    const int n0   = blockIdx.x * BN;

    float acc[TM][TN];
    #pragma unroll
    for (int i = 0; i < TM; i++)
        #pragma unroll
        for (int j = 0; j < TN; j++) acc[i][j] = 0.f;

    #pragma unroll 1
    for (int seg = 0; seg < 2; seg++) {
        const float* A = seg ? A1 : A0;
        const float* W = seg ? W1 : W0;
        const int lda  = seg ? lda1 : lda0;
        const int ldw  = seg ? ldw1 : ldw0;
        const int K    = seg ? K1 : K0;
        if (K == 0) continue;

        for (int k0 = 0; k0 < K; k0 += BK) {
            // load A tile (BM x BK) as float4 along K
            constexpr int ANUM = BM * BK4;
            #pragma unroll
            for (int it = 0; it < (ANUM + NT - 1) / NT; ++it) {
                int i = tid + it * NT;
                if (ANUM % NT == 0 || i < ANUM) {
                    int row = i / BK4, kq = i % BK4;
                    const float4 v = *reinterpret_cast<const float4*>(
                        A + (size_t)(m0 + row) * lda + k0 + kq * 4);
                    As[kq * 4 + 0][row] = v.x;
                    As[kq * 4 + 1][row] = v.y;
                    As[kq * 4 + 2][row] = v.z;
                    As[kq * 4 + 3][row] = v.w;
                }
            }
            // load W tile (BN x BK), zero-fill rows beyond N
            constexpr int WNUM = BN * BK4;
            #pragma unroll
            for (int it = 0; it < (WNUM + NT - 1) / NT; ++it) {
                int i = tid + it * NT;
                if (WNUM % NT == 0 || i < WNUM) {
                    int row = i / BK4, kq = i % BK4;
                    float4 v = make_float4(0.f, 0.f, 0.f, 0.f);
                    if (n0 + row < N)
                        v = *reinterpret_cast<const float4*>(
                            W + (size_t)(n0 + row) * ldw + k0 + kq * 4);
                    Ws[kq * 4 + 0][row] = v.x;
                    Ws[kq * 4 + 1][row] = v.y;
                    Ws[kq * 4 + 2][row] = v.z;
                    Ws[kq * 4 + 3][row] = v.w;
                }
            }
            __syncthreads();

            #pragma unroll
            for (int k = 0; k < BK; k++) {
                float af[TM], wf[TN];
                #pragma unroll
                for (int i = 0; i < TM; i += 4) {
                    float4 v = *reinterpret_cast<const float4*>(&As[k][trow * TM + i]);
                    af[i] = v.x; af[i + 1] = v.y; af[i + 2] = v.z; af[i + 3] = v.w;
                }
                #pragma unroll
                for (int j = 0; j < TN; j += 4) {
                    float4 v = *reinterpret_cast<const float4*>(&Ws[k][tcol * TN + j]);
                    wf[j] = v.x; wf[j + 1] = v.y; wf[j + 2] = v.z; wf[j + 3] = v.w;
                }
                #pragma unroll
                for (int i = 0; i < TM; i++)
                    #pragma unroll
                    for (int j = 0; j < TN; j++)
                        acc[i][j] = fmaf(af[i], wf[j], acc[i][j]);
            }
            __syncthreads();
        }
    }

    // epilogue
    #pragma unroll
    for (int i = 0; i < TM; i++) {
        int m = m0 + trow * TM + i;
        #pragma unroll
        for (int j = 0; j < TN; j++) {
            int n = n0 + tcol * TN + j;
            if (n < N) {
                float v = acc[i][j];
                if (EPI == 1) {
                    v += aux0[(size_t)idxp[m] * 1024 + n];
                } else if (bias) {
                    v += bias[n];
                }
                if (ACT == 1) v = fmaxf(v, 0.f);
                if (EPI == 2) {
                    float u = tanhf(aux0[(size_t)m * 256 + n] + v);
                    v = u * aux1[(size_t)m * 512 + 256 + n];
                }
                C[(size_t)m * ldc + n] = v;
            }
        }
    }
}

// ---------------------------------------------------------------------------
// Final heads: pol = pol2 @ w_p^T + b_p (3), val = val2 @ w_v^T + b_v (1)
// 64 rows per 256-thread block, staged through padded smem.
// ---------------------------------------------------------------------------
__global__ void k_heads(const float* __restrict__ pol2, const float* __restrict__ val2,
                        const float* __restrict__ w_p, const float* __restrict__ b_p,
                        const float* __restrict__ w_v, const float* __restrict__ b_v,
                        float* __restrict__ out_val, float* __restrict__ out_pol) {
    __shared__ float sp[64][65];
    __shared__ float sv[64][33];
    int r0 = blockIdx.x * 64;
    for (int i = threadIdx.x; i < 64 * 64; i += blockDim.x)
        sp[i >> 6][i & 63] = pol2[(size_t)r0 * 64 + i];
    for (int i = threadIdx.x; i < 64 * 32; i += blockDim.x)
        sv[i >> 5][i & 31] = val2[(size_t)r0 * 32 + i];
    __syncthreads();
    int t = threadIdx.x;
    if (t < 64) {
        int b = r0 + t;
        float p0 = b_p[0], p1 = b_p[1], p2 = b_p[2];
        #pragma unroll
        for (int k = 0; k < 64; k++) {
            float x = sp[t][k];
            p0 = fmaf(x, w_p[k], p0);
            p1 = fmaf(x, w_p[64 + k], p1);
            p2 = fmaf(x, w_p[128 + k], p2);
        }
        out_pol[(size_t)b * 3 + 0] = p0;
        out_pol[(size_t)b * 3 + 1] = p1;
        out_pol[(size_t)b * 3 + 2] = p2;
        float v = b_v[0];
        #pragma unroll
        for (int k = 0; k < 32; k++) v = fmaf(sv[t][k], w_v[k], v);
        out_val[b] = v;
    }
}

// ---------------------------------------------------------------------------
// host launcher
// ---------------------------------------------------------------------------
extern "C" void kernel_launch(void* const* d_in, const int* in_sizes, int n_in,
                              void* d_out, int out_size) {
    const float* img   = (const float*)d_in[0];
    const int*   idx   = (const int*)  d_in[1];
    const float* hx_in = (const float*)d_in[2];
    const float* cx_in = (const float*)d_in[3];
    const float* query = (const float*)d_in[4];
    const float* emb   = (const float*)d_in[5];
    const float* w_ta  = (const float*)d_in[6];
    const float* b_ta  = (const float*)d_in[7];
    const float* w_ih  = (const float*)d_in[8];
    const float* w_hh  = (const float*)d_in[9];
    const float* b_ih  = (const float*)d_in[10];
    const float* b_hh  = (const float*)d_in[11];
    const float* w_q   = (const float*)d_in[12];
    const float* b_q   = (const float*)d_in[13];
    const float* w_k   = (const float*)d_in[14];
    const float* b_k   = (const float*)d_in[15];
    const float* w_ba  = (const float*)d_in[16];
    const float* b_ba  = (const float*)d_in[17];
    const float* w_at  = (const float*)d_in[18];
    const float* b_at  = (const float*)d_in[19];
    const float* w_p1  = (const float*)d_in[20];
    const float* b_p1  = (const float*)d_in[21];
    const float* w_p2  = (const float*)d_in[22];
    const float* b_p2  = (const float*)d_in[23];
    const float* w_p   = (const float*)d_in[24];
    const float* b_p   = (const float*)d_in[25];
    const float* w_v1  = (const float*)d_in[26];
    const float* b_v1  = (const float*)d_in[27];
    const float* w_v2  = (const float*)d_in[28];
    const float* b_v2  = (const float*)d_in[29];
    const float* w_v   = (const float*)d_in[30];
    const float* b_v   = (const float*)d_in[31];

    const int B = in_sizes[0] / 256;  // 32768

    float* S = nullptr;
    cudaGetSymbolAddress((void**)&S, g_scratch);

    float* tab   = S + O_TAB;
    float* pre2  = S + O_PRE2;
    float* fus   = S + O_FUSION;
    float* gates = S + O_GATES;
    float* mlp   = S + O_MLP;
    float* qout  = S + O_QOUT;
    float* avec  = S + O_AVEC;
    float* attnw = S + O_ATTNW;
    float* pol1  = S + O_POL1;
    float* pol2  = S + O_POL2;
    float* val1  = S + O_VAL1;
    float* val2  = S + O_VAL2;

    float* out   = (float*)d_out;
    float* o_val = out;                              // [B]
    float* o_pol = out + (size_t)B;                  // [B,3]
    float* o_hx  = out + (size_t)B * 4;              // [B,256]
    float* o_cx  = o_hx + (size_t)B * 256;           // [B,256]

    const int EW   = B * 256;
    const dim3 blk(256);

    // K0: tables
    k0_tables<<<1, 1024>>>(emb, w_ta, b_ta, w_ih, b_ih, b_hh, tab, pre2);

    // K1: gated_fusion
    k_fusion<<<(EW + 255) / 256, blk>>>(img, idx, tab, fus, EW);

    // K2: gates = fus @ w_ih[:, :256]^T + hx @ w_hh^T + pre2[idx]
    gemm_k<128, 128, 16, 8, 8, 0, 1><<<dim3(1024 / 128, B / 128), 256>>>(
        B, 1024,
        fus, 256, w_ih, 512, 256,
        hx_in, 256, w_hh, 256, 256,
        nullptr, pre2, nullptr, idx, gates, 1024);

    // K3: LSTM activations -> hx, cx (directly into output)
    k_lstm<<<(EW + 255) / 256, blk>>>(gates, cx_in, o_hx, o_cx, EW);

    // K4: mlp_attn = relu([fus | hx] @ w_ba^T + b_ba)
    gemm_k<128, 128, 16, 8, 8, 1, 0><<<dim3(512 / 128, B / 128), 256>>>(
        B, 512,
        fus, 256, w_ba, 512, 256,
        o_hx, 256, w_ba + 256, 512, 256,
        b_ba, nullptr, nullptr, nullptr, mlp, 512);

    // K5: qout = relu(query @ w_q^T + b_q)
    gemm_k<128, 128, 16, 8, 8, 1, 0><<<dim3(2, B / 128), 256>>>(
        B, 256,
        query, 256, w_q, 256, 256,
        nullptr, 0, nullptr, 0, 0,
        b_q, nullptr, nullptr, nullptr, qout, 256);

    // K6: avec = tanh(qout + relu(key @ w_k^T + b_k)) * val   (key/val from mlp)
    gemm_k<128, 128, 16, 8, 8, 1, 2><<<dim3(2, B / 128), 256>>>(
        B, 256,
        mlp, 512, w_k, 256, 256,
        nullptr, 0, nullptr, 0, 0,
        b_k, qout, mlp, nullptr, avec, 256);

    // K7: attnw = relu([avec | hx] @ w_at^T + b_at)
    gemm_k<128, 128, 16, 8, 8, 1, 0><<<dim3(2, B / 128), 256>>>(
        B, 256,
        avec, 256, w_at, 512, 256,
        o_hx, 256, w_at + 256, 512, 256,
        b_at, nullptr, nullptr, nullptr, attnw, 256);

    // K8: pol1 = relu(attnw @ w_p1^T + b_p1)   N=128
    gemm_k<128, 128, 16, 8, 8, 1, 0><<<dim3(1, B / 128), 256>>>(
        B, 128,
        attnw, 256, w_p1, 256, 256,
        nullptr, 0, nullptr, 0, 0,
        b_p1, nullptr, nullptr, nullptr, pol1, 128);

    // K9: pol2 = relu(pol1 @ w_p2^T + b_p2)    N=64
    gemm_k<128, 64, 16, 8, 4, 1, 0><<<dim3(1, B / 128), 256>>>(
        B, 64,
        pol1, 128, w_p2, 128, 128,
        nullptr, 0, nullptr, 0, 0,
        b_p2, nullptr, nullptr, nullptr, pol2, 64);

    // K10: val1 = relu(attnw @ w_v1^T + b_v1)  N=64
    gemm_k<128, 64, 16, 8, 4, 1, 0><<<dim3(1, B / 128), 256>>>(
        B, 64,
        attnw, 256, w_v1, 256, 256,
        nullptr, 0, nullptr, 0, 0,
        b_v1, nullptr, nullptr, nullptr, val1, 64);

    // K11: val2 = relu(val1 @ w_v2^T + b_v2)   N=32 (guarded)
    gemm_k<128, 64, 16, 8, 4, 1, 0><<<dim3(1, B / 128), 256>>>(
        B, 32,
        val1, 64, w_v2, 64, 64,
        nullptr, 0, nullptr, 0, 0,
        b_v2, nullptr, nullptr, nullptr, val2, 32);

    // K12: final heads
    k_heads<<<B / 64, 256>>>(pol2, val2, w_p, b_p, w_v, b_v, o_val, o_pol);
}

// round 3
// speedup vs baseline: 1.6751x; 1.6751x over previous
#include <cuda_runtime.h>
#include <cuda_bf16.h>
#include <cstdint>
#include <math.h>

// ---------------------------------------------------------------------------
// Actor_Critic fused pipeline — bf16x2 split-precision tensor-core GEMMs.
//
// Algebraic reductions vs reference:
//  - gated_att has only 4 distinct rows -> 4x256 table.
//  - gated_att @ w_ih[:,256:512] + biases -> pre2[4][1024] table; big GEMM K=512.
// Precision: each fp32 operand split into bf16 hi+lo; 3 MMA passes
//   (ah*bh + al*bh + ah*bl) -> ~2^-16 relative error.
// ---------------------------------------------------------------------------

constexpr size_t S_B = 32768;

constexpr size_t O_TAB    = 0;                       // 4*256
constexpr size_t O_PRE2   = 1024;                    // 4*1024
constexpr size_t O_FUSION = 8192;                    // B*256
constexpr size_t O_GATES  = O_FUSION + S_B * 256;    // B*1024
constexpr size_t O_MLP    = O_GATES  + S_B * 1024;   // B*512
constexpr size_t O_QOUT   = O_MLP    + S_B * 512;    // B*256
constexpr size_t O_AVEC   = O_QOUT   + S_B * 256;    // B*256
constexpr size_t O_ATTNW  = O_AVEC   + S_B * 256;    // B*256
constexpr size_t O_POL1   = O_ATTNW  + S_B * 256;    // B*128
constexpr size_t O_POL2   = O_POL1   + S_B * 128;    // B*64
constexpr size_t O_VAL1   = O_POL2   + S_B * 64;     // B*64
constexpr size_t O_VAL2   = O_VAL1   + S_B * 64;     // B*32
constexpr size_t O_END    = O_VAL2   + S_B * 32;

__device__ float g_scratch[O_END];

__device__ __forceinline__ float sigmoidf_(float x) { return 1.f / (1.f + expf(-x)); }

// ---------------------------------------------------------------------------
// K0: build gated_att table (4x256) and pre2 table (4x1024). One block.
// ---------------------------------------------------------------------------
__global__ void k0_tables(const float* __restrict__ emb,  const float* __restrict__ w_ta,
                          const float* __restrict__ b_ta, const float* __restrict__ w_ih,
                          const float* __restrict__ b_ih, const float* __restrict__ b_hh,
                          float* __restrict__ tab, float* __restrict__ pre2) {
    int t = threadIdx.x;  // 1024 threads
    {
        int r = t >> 8, j = t & 255;
        float s = b_ta[j];
        #pragma unroll
        for (int k = 0; k < 25; k++) s += emb[r * 25 + k] * w_ta[j * 25 + k];
        tab[t] = sigmoidf_(s);
    }
    __syncthreads();
    {
        int j = t;  // 0..1023
        const float* wrow = &w_ih[(size_t)j * 512 + 256];
        float base = b_ih[j] + b_hh[j];
        for (int r = 0; r < 4; r++) {
            const float* tr = &tab[r * 256];
            float s = base;
            for (int k = 0; k < 256; k++) s += tr[k] * wrow[k];
            pre2[r * 1024 + j] = s;
        }
    }
}

// ---------------------------------------------------------------------------
// K1: gated_fusion = img_feat * tab[idx]
// ---------------------------------------------------------------------------
__global__ void k_fusion(const float* __restrict__ img, const int* __restrict__ idx,
                         const float* __restrict__ tab, float* __restrict__ out, int total) {
    int i = blockIdx.x * blockDim.x + threadIdx.x;
    if (i >= total) return;
    int b = i >> 8, j = i & 255;
    out[i] = img[i] * tab[idx[b] * 256 + j];
}

// ---------------------------------------------------------------------------
// K3: LSTM activation, vectorized float4 (4 units per thread)
// ---------------------------------------------------------------------------
__global__ void k_lstm(const float* __restrict__ gates, const float* __restrict__ cx_in,
                       float* __restrict__ hx_out, float* __restrict__ cx_out, int totalq) {
    int i = blockIdx.x * blockDim.x + threadIdx.x;
    if (i >= totalq) return;
    int b = i >> 6, j = (i & 63) << 2;
    const float* g = gates + (size_t)b * 1024 + j;
    float4 gi = *reinterpret_cast<const float4*>(g);
    float4 gf = *reinterpret_cast<const float4*>(g + 256);
    float4 gg = *reinterpret_cast<const float4*>(g + 512);
    float4 go = *reinterpret_cast<const float4*>(g + 768);
    float4 c0 = *reinterpret_cast<const float4*>(cx_in + (size_t)b * 256 + j);
    float4 ho, co;
    {
        float c = sigmoidf_(gf.x) * c0.x + sigmoidf_(gi.x) * tanhf(gg.x);
        co.x = c; ho.x = sigmoidf_(go.x) * tanhf(c);
    }
    {
        float c = sigmoidf_(gf.y) * c0.y + sigmoidf_(gi.y) * tanhf(gg.y);
        co.y = c; ho.y = sigmoidf_(go.y) * tanhf(c);
    }
    {
        float c = sigmoidf_(gf.z) * c0.z + sigmoidf_(gi.z) * tanhf(gg.z);
        co.z = c; ho.z = sigmoidf_(go.z) * tanhf(c);
    }
    {
        float c = sigmoidf_(gf.w) * c0.w + sigmoidf_(gi.w) * tanhf(gg.w);
        co.w = c; ho.w = sigmoidf_(go.w) * tanhf(c);
    }
    *reinterpret_cast<float4*>(hx_out + (size_t)b * 256 + j) = ho;
    *reinterpret_cast<float4*>(cx_out + (size_t)b * 256 + j) = co;
}

// ---------------------------------------------------------------------------
// MMA helpers
// ---------------------------------------------------------------------------
__device__ __forceinline__ void ldm4(uint32_t* r, uint32_t addr) {
    asm volatile("ldmatrix.sync.aligned.m8n8.x4.shared.b16 {%0,%1,%2,%3}, [%4];"
                 : "=r"(r[0]), "=r"(r[1]), "=r"(r[2]), "=r"(r[3]) : "r"(addr));
}

__device__ __forceinline__ void mma16816(float* c, const uint32_t* a, uint32_t b0, uint32_t b1) {
    asm volatile(
        "mma.sync.aligned.m16n8k16.row.col.f32.bf16.bf16.f32 "
        "{%0,%1,%2,%3}, {%4,%5,%6,%7}, {%8,%9}, {%0,%1,%2,%3};"
        : "+f"(c[0]), "+f"(c[1]), "+f"(c[2]), "+f"(c[3])
        : "r"(a[0]), "r"(a[1]), "r"(a[2]), "r"(a[3]), "r"(b0), "r"(b1));
}

__device__ __forceinline__ void split_store(float4 v, __nv_bfloat16* ph, __nv_bfloat16* pl) {
    unsigned short h[4], l[4];
    const float f[4] = {v.x, v.y, v.z, v.w};
    #pragma unroll
    for (int i = 0; i < 4; i++) {
        __nv_bfloat16 hb = __float2bfloat16(f[i]);
        __nv_bfloat16 lb = __float2bfloat16(f[i] - __bfloat162float(hb));
        h[i] = __bfloat16_as_ushort(hb);
        l[i] = __bfloat16_as_ushort(lb);
    }
    uint2 uh, ul;
    uh.x = (uint32_t)h[0] | ((uint32_t)h[1] << 16);
    uh.y = (uint32_t)h[2] | ((uint32_t)h[3] << 16);
    ul.x = (uint32_t)l[0] | ((uint32_t)l[1] << 16);
    ul.y = (uint32_t)l[2] | ((uint32_t)l[3] << 16);
    *reinterpret_cast<uint2*>(ph) = uh;
    *reinterpret_cast<uint2*>(pl) = ul;
}

// ---------------------------------------------------------------------------
// Tensor-core GEMM:  C[M,N] = epi( sum_seg A_seg[M,Kseg] @ W_seg[N,Kseg]^T )
// bf16x2 split precision, 3 MMA passes. BM=128 fixed. 256 threads, 8 warps 4x2.
// EPI 0: + bias (if non-null), optional relu (ACT==1)
// EPI 1: + aux0[idxp[m]*1024 + n]     (gates + pre2 table; bias folded in)
// EPI 2: (+bias, relu) -> u = tanh(aux0[m*256+n] + v); out = u * aux1[m*512+256+n]
// K segments must be multiples of 32; M multiple of 128.
// ---------------------------------------------------------------------------
template <int BN, int ACT, int EPI>
__global__ void __launch_bounds__(256)
mma_gemm(int M, int N,
         const float* __restrict__ A0, int lda0, const float* __restrict__ W0, int ldw0, int K0,
         const float* __restrict__ A1, int lda1, const float* __restrict__ W1, int ldw1, int K1,
         const float* __restrict__ bias, const float* __restrict__ aux0,
         const float* __restrict__ aux1, const int* __restrict__ idxp,
         float* __restrict__ C, int ldc) {
    constexpr int WN   = BN / 2;    // warp n-extent (2 warps in n)
    constexpr int NT8  = WN / 8;    // n8 tiles per warp
    constexpr int N16T = WN / 16;   // n16 ldmatrix tiles per warp
    constexpr int WIT  = BN / 32;   // float4 W-load iterations
    constexpr int SSTR = 40;        // bf16 elems per smem row (80B, conflict-free)

    __shared__ __nv_bfloat16 sAh[128 * SSTR], sAl[128 * SSTR];
    __shared__ __nv_bfloat16 sWh[BN * SSTR],  sWl[BN * SSTR];

    const int tid  = threadIdx.x;
    const int lane = tid & 31;
    const int wid  = tid >> 5;
    const int wm = wid & 3, wn = wid >> 2;  // 4 x 2 warp grid
    const int m0 = blockIdx.y * 128;
    const int n0 = blockIdx.x * BN;

    float acc[2][NT8][4];
    #pragma unroll
    for (int i = 0; i < 2; i++)
        #pragma unroll
        for (int j = 0; j < NT8; j++)
            #pragma unroll
            for (int q = 0; q < 4; q++) acc[i][j][q] = 0.f;

    const int nc0 = K0 >> 5;
    const int NC  = nc0 + (K1 >> 5);

    float4 ra[4];
    float4 rw[WIT];

    auto loadc = [&](int c) {
        const float *A, *W;
        int lda, ldw, kc;
        if (c < nc0) { A = A0; W = W0; lda = lda0; ldw = ldw0; kc = c << 5; }
        else         { A = A1; W = W1; lda = lda1; ldw = ldw1; kc = (c - nc0) << 5; }
        #pragma unroll
        for (int it = 0; it < 4; it++) {
            int idx = tid + it * 256;
            int row = idx >> 3, kq = idx & 7;
            ra[it] = *reinterpret_cast<const float4*>(A + (size_t)(m0 + row) * lda + kc + kq * 4);
        }
        #pragma unroll
        for (int it = 0; it < WIT; it++) {
            int idx = tid + it * 256;
            int row = idx >> 3, kq = idx & 7;
            rw[it] = (n0 + row < N)
                ? *reinterpret_cast<const float4*>(W + (size_t)(n0 + row) * ldw + kc + kq * 4)
                : make_float4(0.f, 0.f, 0.f, 0.f);
        }
    };

    const uint32_t bAh = (uint32_t)__cvta_generic_to_shared(sAh);
    const uint32_t bAl = (uint32_t)__cvta_generic_to_shared(sAl);
    const uint32_t bWh = (uint32_t)__cvta_generic_to_shared(sWh);
    const uint32_t bWl = (uint32_t)__cvta_generic_to_shared(sWl);

    loadc(0);
    for (int c = 0; c < NC; c++) {
        __syncthreads();
        #pragma unroll
        for (int it = 0; it < 4; it++) {
            int idx = tid + it * 256;
            int row = idx >> 3, kq = idx & 7;
            split_store(ra[it], &sAh[row * SSTR + kq * 4], &sAl[row * SSTR + kq * 4]);
        }
        #pragma unroll
        for (int it = 0; it < WIT; it++) {
            int idx = tid + it * 256;
            int row = idx >> 3, kq = idx & 7;
            split_store(rw[it], &sWh[row * SSTR + kq * 4], &sWl[row * SSTR + kq * 4]);
        }
        __syncthreads();
        if (c + 1 < NC) loadc(c + 1);

        #pragma unroll
        for (int kk = 0; kk < 32; kk += 16) {
            uint32_t ah[2][4], al[2][4];
            #pragma unroll
            for (int mt = 0; mt < 2; mt++) {
                int row = wm * 32 + mt * 16 + (lane & 15);
                int col = kk + ((lane >> 4) << 3);
                uint32_t off = (uint32_t)(row * SSTR + col) * 2u;
                ldm4(ah[mt], bAh + off);
                ldm4(al[mt], bAl + off);
            }
            uint32_t bh[N16T][4], bl[N16T][4];
            #pragma unroll
            for (int t = 0; t < N16T; t++) {
                int row = wn * WN + t * 16 + (lane & 15);
                int col = kk + ((lane >> 4) << 3);
                uint32_t off = (uint32_t)(row * SSTR + col) * 2u;
                ldm4(bh[t], bWh + off);
                ldm4(bl[t], bWl + off);
            }
            #pragma unroll
            for (int mt = 0; mt < 2; mt++)
                #pragma unroll
                for (int nt = 0; nt < NT8; nt++) {
                    int t = nt >> 1, hs = nt & 1;
                    mma16816(acc[mt][nt], ah[mt], bh[t][hs], bh[t][2 + hs]);
                    mma16816(acc[mt][nt], al[mt], bh[t][hs], bh[t][2 + hs]);
                    mma16816(acc[mt][nt], ah[mt], bl[t][hs], bl[t][2 + hs]);
                }
        }
    }

    // epilogue
    #pragma unroll
    for (int mt = 0; mt < 2; mt++) {
        int r0 = m0 + wm * 32 + mt * 16 + (lane >> 2);
        int r1 = r0 + 8;
        int ib0 = 0, ib1 = 0;
        if (EPI == 1) { ib0 = idxp[r0]; ib1 = idxp[r1]; }
        #pragma unroll
        for (int nt = 0; nt < NT8; nt++) {
            int cc = n0 + wn * WN + nt * 8 + ((lane & 3) << 1);
            if (cc < N) {
                float v0 = acc[mt][nt][0], v1 = acc[mt][nt][1];
                float v2 = acc[mt][nt][2], v3 = acc[mt][nt][3];
                #pragma unroll
                for (int p = 0; p < 2; p++) {
                    int r  = p ? r1 : r0;
                    int ib = p ? ib1 : ib0;
                    float x = p ? v2 : v0;
                    float y = p ? v3 : v1;
                    if (EPI == 1) {
                        x += aux0[(size_t)ib * 1024 + cc];
                        y += aux0[(size_t)ib * 1024 + cc + 1];
                    } else if (bias) {
                        x += bias[cc];
                        y += bias[cc + 1];
                    }
                    if (ACT) { x = fmaxf(x, 0.f); y = fmaxf(y, 0.f); }
                    if (EPI == 2) {
                        x = tanhf(aux0[(size_t)r * 256 + cc] + x)     * aux1[(size_t)r * 512 + 256 + cc];
                        y = tanhf(aux0[(size_t)r * 256 + cc + 1] + y) * aux1[(size_t)r * 512 + 256 + cc + 1];
                    }
                    *reinterpret_cast<float2*>(&C[(size_t)r * ldc + cc]) = make_float2(x, y);
                }
            }
        }
    }
}

// ---------------------------------------------------------------------------
// Final heads: pol = pol2 @ w_p^T + b_p (3), val = val2 @ w_v^T + b_v (1)
// ---------------------------------------------------------------------------
__global__ void k_heads(const float* __restrict__ pol2, const float* __restrict__ val2,
                        const float* __restrict__ w_p, const float* __restrict__ b_p,
                        const float* __restrict__ w_v, const float* __restrict__ b_v,
                        float* __restrict__ out_val, float* __restrict__ out_pol) {
    __shared__ float sp[64][65];
    __shared__ float sv[64][33];
    int r0 = blockIdx.x * 64;
    for (int i = threadIdx.x; i < 64 * 64; i += blockDim.x)
        sp[i >> 6][i & 63] = pol2[(size_t)r0 * 64 + i];
    for (int i = threadIdx.x; i < 64 * 32; i += blockDim.x)
        sv[i >> 5][i & 31] = val2[(size_t)r0 * 32 + i];
    __syncthreads();
    int t = threadIdx.x;
    if (t < 64) {
        int b = r0 + t;
        float p0 = b_p[0], p1 = b_p[1], p2 = b_p[2];
        #pragma unroll
        for (int k = 0; k < 64; k++) {
            float x = sp[t][k];
            p0 = fmaf(x, w_p[k], p0);
            p1 = fmaf(x, w_p[64 + k], p1);
            p2 = fmaf(x, w_p[128 + k], p2);
        }
        out_pol[(size_t)b * 3 + 0] = p0;
        out_pol[(size_t)b * 3 + 1] = p1;
        out_pol[(size_t)b * 3 + 2] = p2;
        float v = b_v[0];
        #pragma unroll
        for (int k = 0; k < 32; k++) v = fmaf(sv[t][k], w_v[k], v);
        out_val[b] = v;
    }
}

// ---------------------------------------------------------------------------
// host launcher
// ---------------------------------------------------------------------------
extern "C" void kernel_launch(void* const* d_in, const int* in_sizes, int n_in,
                              void* d_out, int out_size) {
    const float* img   = (const float*)d_in[0];
    const int*   idx   = (const int*)  d_in[1];
    const float* hx_in = (const float*)d_in[2];
    const float* cx_in = (const float*)d_in[3];
    const float* query = (const float*)d_in[4];
    const float* emb   = (const float*)d_in[5];
    const float* w_ta  = (const float*)d_in[6];
    const float* b_ta  = (const float*)d_in[7];
    const float* w_ih  = (const float*)d_in[8];
    const float* w_hh  = (const float*)d_in[9];
    const float* b_ih  = (const float*)d_in[10];
    const float* b_hh  = (const float*)d_in[11];
    const float* w_q   = (const float*)d_in[12];
    const float* b_q   = (const float*)d_in[13];
    const float* w_k   = (const float*)d_in[14];
    const float* b_k   = (const float*)d_in[15];
    const float* w_ba  = (const float*)d_in[16];
    const float* b_ba  = (const float*)d_in[17];
    const float* w_at  = (const float*)d_in[18];
    const float* b_at  = (const float*)d_in[19];
    const float* w_p1  = (const float*)d_in[20];
    const float* b_p1  = (const float*)d_in[21];
    const float* w_p2  = (const float*)d_in[22];
    const float* b_p2  = (const float*)d_in[23];
    const float* w_p   = (const float*)d_in[24];
    const float* b_p   = (const float*)d_in[25];
    const float* w_v1  = (const float*)d_in[26];
    const float* b_v1  = (const float*)d_in[27];
    const float* w_v2  = (const float*)d_in[28];
    const float* b_v2  = (const float*)d_in[29];
    const float* w_v   = (const float*)d_in[30];
    const float* b_v   = (const float*)d_in[31];

    const int B = in_sizes[0] / 256;  // 32768

    float* S = nullptr;
    cudaGetSymbolAddress((void**)&S, g_scratch);

    float* tab   = S + O_TAB;
    float* pre2  = S + O_PRE2;
    float* fus   = S + O_FUSION;
    float* gates = S + O_GATES;
    float* mlp   = S + O_MLP;
    float* qout  = S + O_QOUT;
    float* avec  = S + O_AVEC;
    float* attnw = S + O_ATTNW;
    float* pol1  = S + O_POL1;
    float* pol2  = S + O_POL2;
    float* val1  = S + O_VAL1;
    float* val2  = S + O_VAL2;

    float* out   = (float*)d_out;
    float* o_val = out;                     // [B]
    float* o_pol = out + (size_t)B;         // [B,3]
    float* o_hx  = out + (size_t)B * 4;     // [B,256]
    float* o_cx  = o_hx + (size_t)B * 256;  // [B,256]

    const int EW = B * 256;

    // K0: tables
    k0_tables<<<1, 1024>>>(emb, w_ta, b_ta, w_ih, b_ih, b_hh, tab, pre2);

    // K1: gated_fusion
    k_fusion<<<(EW + 255) / 256, 256>>>(img, idx, tab, fus, EW);

    // K2: gates = fus @ w_ih[:, :256]^T + hx @ w_hh^T + pre2[idx]
    mma_gemm<128, 0, 1><<<dim3(8, B / 128), 256>>>(
        B, 1024,
        fus, 256, w_ih, 512, 256,
        hx_in, 256, w_hh, 256, 256,
        nullptr, pre2, nullptr, idx, gates, 1024);

    // K3: LSTM activations -> hx, cx (directly into output)
    k_lstm<<<(B * 64 + 255) / 256, 256>>>(gates, cx_in, o_hx, o_cx, B * 64);

    // K4: mlp_attn = relu([fus | hx] @ w_ba^T + b_ba)
    mma_gemm<128, 1, 0><<<dim3(4, B / 128), 256>>>(
        B, 512,
        fus, 256, w_ba, 512, 256,
        o_hx, 256, w_ba + 256, 512, 256,
        b_ba, nullptr, nullptr, nullptr, mlp, 512);

    // K5: qout = relu(query @ w_q^T + b_q)
    mma_gemm<128, 1, 0><<<dim3(2, B / 128), 256>>>(
        B, 256,
        query, 256, w_q, 256, 256,
        nullptr, 0, nullptr, 0, 0,
        b_q, nullptr, nullptr, nullptr, qout, 256);

    // K6: avec = tanh(qout + relu(key @ w_k^T + b_k)) * val   (key/val from mlp)
    mma_gemm<128, 1, 2><<<dim3(2, B / 128), 256>>>(
        B, 256,
        mlp, 512, w_k, 256, 256,
        nullptr, 0, nullptr, 0, 0,
        b_k, qout, mlp, nullptr, avec, 256);

    // K7: attnw = relu([avec | hx] @ w_at^T + b_at)
    mma_gemm<128, 1, 0><<<dim3(2, B / 128), 256>>>(
        B, 256,
        avec, 256, w_at, 512, 256,
        o_hx, 256, w_at + 256, 512, 256,
        b_at, nullptr, nullptr, nullptr, attnw, 256);

    // K8: pol1 = relu(attnw @ w_p1^T + b_p1)   N=128
    mma_gemm<128, 1, 0><<<dim3(1, B / 128), 256>>>(
        B, 128,
        attnw, 256, w_p1, 256, 256,
        nullptr, 0, nullptr, 0, 0,
        b_p1, nullptr, nullptr, nullptr, pol1, 128);

    // K9: pol2 = relu(pol1 @ w_p2^T + b_p2)    N=64
    mma_gemm<64, 1, 0><<<dim3(1, B / 128), 256>>>(
        B, 64,
        pol1, 128, w_p2, 128, 128,
        nullptr, 0, nullptr, 0, 0,
        b_p2, nullptr, nullptr, nullptr, pol2, 64);

    // K10: val1 = relu(attnw @ w_v1^T + b_v1)  N=64
    mma_gemm<64, 1, 0><<<dim3(1, B / 128), 256>>>(
        B, 64,
        attnw, 256, w_v1, 256, 256,
        nullptr, 0, nullptr, 0, 0,
        b_v1, nullptr, nullptr, nullptr, val1, 64);

    // K11: val2 = relu(val1 @ w_v2^T + b_v2)   N=32 (guarded)
    mma_gemm<64, 1, 0><<<dim3(1, B / 128), 256>>>(
        B, 32,
        val1, 64, w_v2, 64, 64,
        nullptr, 0, nullptr, 0, 0,
        b_v2, nullptr, nullptr, nullptr, val2, 32);

    // K12: final heads
    k_heads<<<B / 64, 256>>>(pol2, val2, w_p, b_p, w_v, b_v, o_val, o_pol);
}

// round 5
// speedup vs baseline: 1.8946x; 1.1310x over previous
#include <cuda_runtime.h>
#include <cuda_bf16.h>
#include <cstdint>
#include <math.h>

// ---------------------------------------------------------------------------
// Actor_Critic — bf16x2 split-precision MMA pipeline, persistent bf16 format.
//  - weights pre-split once to bf16 hi/lo (padded, compacted)
//  - activations flow as bf16 hi/lo between GEMMs (epilogue emits them)
//  - GEMM main loop: cp.async double-buffered, zero conversions inside
// ---------------------------------------------------------------------------

constexpr size_t S_B = 32768;

// fp32 scratch
constexpr size_t F_TAB   = 0;
constexpr size_t F_PRE2  = 1024;
constexpr size_t F_GATES = 8192;
constexpr size_t F_MLP   = F_GATES + S_B * 1024;
constexpr size_t F_QOUT  = F_MLP   + S_B * 512;
constexpr size_t F_POL2  = F_QOUT  + S_B * 256;
constexpr size_t F_VAL2  = F_POL2  + S_B * 64;
constexpr size_t F_END   = F_VAL2  + S_B * 32;
__device__ float g_f32[F_END];

// bf16 scratch: hi at OFF, lo at OFF + B_HALF
constexpr size_t B_WIH  = 0;                       // 1024x256 (compacted cols 0:256)
constexpr size_t B_WHH  = B_WIH  + 1024 * 256;     // 1024x256
constexpr size_t B_WBA  = B_WHH  + 1024 * 256;     // 512x512
constexpr size_t B_WQ   = B_WBA  + 512 * 512;      // 256x256
constexpr size_t B_WK   = B_WQ   + 256 * 256;      // 256x256
constexpr size_t B_WAT  = B_WK   + 256 * 256;      // 256x512
constexpr size_t B_WP1  = B_WAT  + 256 * 512;      // 128x256
constexpr size_t B_WP2  = B_WP1  + 128 * 256;      // 64x128
constexpr size_t B_WV1  = B_WP2  + 64 * 128;       // 64x256
constexpr size_t B_WV2  = B_WV1  + 64 * 256;       // 64x64 (padded from 32 rows)
constexpr size_t B_FUS  = B_WV2  + 64 * 64;        // B*256
constexpr size_t B_HXI  = B_FUS  + S_B * 256;      // B*256
constexpr size_t B_QRY  = B_HXI  + S_B * 256;      // B*256
constexpr size_t B_HXO  = B_QRY  + S_B * 256;      // B*256
constexpr size_t B_MLP  = B_HXO  + S_B * 256;      // B*512
constexpr size_t B_AVEC = B_MLP  + S_B * 512;      // B*256
constexpr size_t B_ATT  = B_AVEC + S_B * 256;      // B*256
constexpr size_t B_POL1 = B_ATT  + S_B * 256;      // B*128
constexpr size_t B_VAL1 = B_POL1 + S_B * 128;      // B*64
constexpr size_t B_HALF = B_VAL1 + S_B * 64;
__device__ __nv_bfloat16 g_bf[2 * B_HALF];

__device__ __forceinline__ float sigmoidf_(float x) { return 1.f / (1.f + expf(-x)); }

__device__ __forceinline__ void bsplit(float v, __nv_bfloat16& h, __nv_bfloat16& l) {
    h = __float2bfloat16(v);
    l = __float2bfloat16(v - __bfloat162float(h));
}
__device__ __forceinline__ uint32_t pack2(__nv_bfloat16 a, __nv_bfloat16 b) {
    return (uint32_t)__bfloat16_as_ushort(a) | ((uint32_t)__bfloat16_as_ushort(b) << 16);
}

// ---------------------------------------------------------------------------
// K0: gated_att table (4x256) + pre2 table (4x1024)
// ---------------------------------------------------------------------------
__global__ void k0_tables(const float* __restrict__ emb,  const float* __restrict__ w_ta,
                          const float* __restrict__ b_ta, const float* __restrict__ w_ih,
                          const float* __restrict__ b_ih, const float* __restrict__ b_hh,
                          float* __restrict__ tab, float* __restrict__ pre2) {
    int t = threadIdx.x;  // 1024
    {
        int r = t >> 8, j = t & 255;
        float s = b_ta[j];
        #pragma unroll
        for (int k = 0; k < 25; k++) s += emb[r * 25 + k] * w_ta[j * 25 + k];
        tab[t] = sigmoidf_(s);
    }
    __syncthreads();
    {
        int j = t;
        const float* wrow = &w_ih[(size_t)j * 512 + 256];
        float base = b_ih[j] + b_hh[j];
        for (int r = 0; r < 4; r++) {
            const float* tr = &tab[r * 256];
            float s = base;
            for (int k = 0; k < 256; k++) s += tr[k] * wrow[k];
            pre2[r * 1024 + j] = s;
        }
    }
}

// ---------------------------------------------------------------------------
// weight split: src fp32 [rows x srcld], take first `cols` of each row,
// write compact bf16 hi/lo [padrows x cols] (rows beyond `rows` zero-filled)
// ---------------------------------------------------------------------------
__global__ void k_wsplit(const float* __restrict__ src, int srcld, int cols, int rows,
                         __nv_bfloat16* __restrict__ h, __nv_bfloat16* __restrict__ l,
                         int total) {
    int i = blockIdx.x * blockDim.x + threadIdx.x;
    if (i >= total) return;
    int r = i / cols, c = i - r * cols;
    float v = (r < rows) ? src[(size_t)r * srcld + c] : 0.f;
    __nv_bfloat16 hh, ll;
    bsplit(v, hh, ll);
    h[i] = hh;
    l[i] = ll;
}

// activation split: straight n elems (float4-vectorized)
__global__ void k_asplit(const float4* __restrict__ src, __nv_bfloat16* __restrict__ h,
                         __nv_bfloat16* __restrict__ l, int nq) {
    int i = blockIdx.x * blockDim.x + threadIdx.x;
    if (i >= nq) return;
    float4 v = src[i];
    __nv_bfloat16 hh[4], ll[4];
    bsplit(v.x, hh[0], ll[0]); bsplit(v.y, hh[1], ll[1]);
    bsplit(v.z, hh[2], ll[2]); bsplit(v.w, hh[3], ll[3]);
    uint2 uh = make_uint2(pack2(hh[0], hh[1]), pack2(hh[2], hh[3]));
    uint2 ul = make_uint2(pack2(ll[0], ll[1]), pack2(ll[2], ll[3]));
    *reinterpret_cast<uint2*>(h + (size_t)i * 4) = uh;
    *reinterpret_cast<uint2*>(l + (size_t)i * 4) = ul;
}

// ---------------------------------------------------------------------------
// K1: gated_fusion = img_feat * tab[idx] -> bf16 hi/lo
// ---------------------------------------------------------------------------
__global__ void k_fusion(const float4* __restrict__ img, const int* __restrict__ idx,
                         const float* __restrict__ tab, __nv_bfloat16* __restrict__ h,
                         __nv_bfloat16* __restrict__ l, int nq) {
    int i = blockIdx.x * blockDim.x + threadIdx.x;
    if (i >= nq) return;
    int b = i >> 6, j4 = (i & 63) << 2;
    float4 g = *reinterpret_cast<const float4*>(tab + idx[b] * 256 + j4);
    float4 v = img[i];
    v.x *= g.x; v.y *= g.y; v.z *= g.z; v.w *= g.w;
    __nv_bfloat16 hh[4], ll[4];
    bsplit(v.x, hh[0], ll[0]); bsplit(v.y, hh[1], ll[1]);
    bsplit(v.z, hh[2], ll[2]); bsplit(v.w, hh[3], ll[3]);
    *reinterpret_cast<uint2*>(h + (size_t)i * 4) = make_uint2(pack2(hh[0], hh[1]), pack2(hh[2], hh[3]));
    *reinterpret_cast<uint2*>(l + (size_t)i * 4) = make_uint2(pack2(ll[0], ll[1]), pack2(ll[2], ll[3]));
}

// ---------------------------------------------------------------------------
// K3: LSTM activation -> hx,cx fp32 (output) + hx bf16 hi/lo (for GEMMs)
// ---------------------------------------------------------------------------
__global__ void k_lstm(const float* __restrict__ gates, const float* __restrict__ cx_in,
                       float* __restrict__ hx_out, float* __restrict__ cx_out,
                       __nv_bfloat16* __restrict__ hxh, __nv_bfloat16* __restrict__ hxl,
                       int totalq) {
    int i = blockIdx.x * blockDim.x + threadIdx.x;
    if (i >= totalq) return;
    int b = i >> 6, j = (i & 63) << 2;
    const float* g = gates + (size_t)b * 1024 + j;
    float4 gi = *reinterpret_cast<const float4*>(g);
    float4 gf = *reinterpret_cast<const float4*>(g + 256);
    float4 gg = *reinterpret_cast<const float4*>(g + 512);
    float4 go = *reinterpret_cast<const float4*>(g + 768);
    float4 c0 = *reinterpret_cast<const float4*>(cx_in + (size_t)b * 256 + j);
    float4 ho, co;
    co.x = sigmoidf_(gf.x) * c0.x + sigmoidf_(gi.x) * tanhf(gg.x); ho.x = sigmoidf_(go.x) * tanhf(co.x);
    co.y = sigmoidf_(gf.y) * c0.y + sigmoidf_(gi.y) * tanhf(gg.y); ho.y = sigmoidf_(go.y) * tanhf(co.y);
    co.z = sigmoidf_(gf.z) * c0.z + sigmoidf_(gi.z) * tanhf(gg.z); ho.z = sigmoidf_(go.z) * tanhf(co.z);
    co.w = sigmoidf_(gf.w) * c0.w + sigmoidf_(gi.w) * tanhf(gg.w); ho.w = sigmoidf_(go.w) * tanhf(co.w);
    size_t o = (size_t)b * 256 + j;
    *reinterpret_cast<float4*>(hx_out + o) = ho;
    *reinterpret_cast<float4*>(cx_out + o) = co;
    __nv_bfloat16 hh[4], ll[4];
    bsplit(ho.x, hh[0], ll[0]); bsplit(ho.y, hh[1], ll[1]);
    bsplit(ho.z, hh[2], ll[2]); bsplit(ho.w, hh[3], ll[3]);
    *reinterpret_cast<uint2*>(hxh + o) = make_uint2(pack2(hh[0], hh[1]), pack2(hh[2], hh[3]));
    *reinterpret_cast<uint2*>(hxl + o) = make_uint2(pack2(ll[0], ll[1]), pack2(ll[2], ll[3]));
}

// ---------------------------------------------------------------------------
// MMA / cp.async helpers
// ---------------------------------------------------------------------------
__device__ __forceinline__ void ldm4(uint32_t* r, uint32_t addr) {
    asm volatile("ldmatrix.sync.aligned.m8n8.x4.shared.b16 {%0,%1,%2,%3}, [%4];"
                 : "=r"(r[0]), "=r"(r[1]), "=r"(r[2]), "=r"(r[3]) : "r"(addr));
}
__device__ __forceinline__ void mma16816(float* c, const uint32_t* a, uint32_t b0, uint32_t b1) {
    asm volatile(
        "mma.sync.aligned.m16n8k16.row.col.f32.bf16.bf16.f32 "
        "{%0,%1,%2,%3}, {%4,%5,%6,%7}, {%8,%9}, {%0,%1,%2,%3};"
        : "+f"(c[0]), "+f"(c[1]), "+f"(c[2]), "+f"(c[3])
        : "r"(a[0]), "r"(a[1]), "r"(a[2]), "r"(a[3]), "r"(b0), "r"(b1));
}
#define CPA16(dst, src) asm volatile("cp.async.cg.shared.global [%0], [%1], 16;\n" :: "r"(dst), "l"(src))
#define CPCOMMIT()      asm volatile("cp.async.commit_group;\n")
#define CPWAIT1()       asm volatile("cp.async.wait_group 1;\n")
#define CPWAIT0()       asm volatile("cp.async.wait_group 0;\n")

// ---------------------------------------------------------------------------
// Tensor-core GEMM: C[M,N] = epi( sum_seg A_seg[M,Kseg] @ W_seg[N,Kseg]^T )
// bf16 hi/lo inputs, 3 MMA passes, cp.async double-buffered. 256 thr, 8 warps.
// EPI 0: +bias/relu; EPI 1: +aux0[idxp[m]*1024+n]; EPI 2: relu -> tanh(aux0+v)*aux1
// OUTM bit0: write fp32 C; bit1: write bf16 Ch/Cl.
// ---------------------------------------------------------------------------
template <int BN, int ACT, int EPI, int OUTM>
__global__ void __launch_bounds__(256)
mma_gemm(int N,
         const __nv_bfloat16* __restrict__ A0h, const __nv_bfloat16* __restrict__ A0l, int lda0,
         const __nv_bfloat16* __restrict__ W0h, const __nv_bfloat16* __restrict__ W0l, int ldw0, int K0,
         const __nv_bfloat16* __restrict__ A1h, const __nv_bfloat16* __restrict__ A1l, int lda1,
         const __nv_bfloat16* __restrict__ W1h, const __nv_bfloat16* __restrict__ W1l, int ldw1, int K1,
         const float* __restrict__ bias, const float* __restrict__ aux0,
         const float* __restrict__ aux1, const int* __restrict__ idxp,
         float* __restrict__ C, __nv_bfloat16* __restrict__ Ch, __nv_bfloat16* __restrict__ Cl,
         int ldc) {
    constexpr int WN     = BN / 2;
    constexpr int NT8    = WN / 8;
    constexpr int N16T   = WN / 16;
    constexpr int SSTR   = 40;                      // bf16 per smem row (80B, conflict-free)
    constexpr int ACH    = 128 * SSTR;              // elems per A array
    constexpr int WCH    = BN * SSTR;
    constexpr int STAGEB = (2 * ACH + 2 * WCH) * 2; // stage bytes
    constexpr int WIT    = (BN * 4) / 256;          // W cp.async iters

    extern __shared__ __nv_bfloat16 smem_dyn[];

    const int tid  = threadIdx.x;
    const int lane = tid & 31;
    const int wid  = tid >> 5;
    const int wm = wid & 3, wn = wid >> 2;
    const int m0 = blockIdx.y * 128;
    const int n0 = blockIdx.x * BN;

    const uint32_t smb = (uint32_t)__cvta_generic_to_shared(smem_dyn);

    float acc[2][NT8][4];
    #pragma unroll
    for (int i = 0; i < 2; i++)
        #pragma unroll
        for (int j = 0; j < NT8; j++)
            #pragma unroll
            for (int q = 0; q < 4; q++) acc[i][j][q] = 0.f;

    const int nc0 = K0 >> 5;
    const int NC  = nc0 + (K1 >> 5);

    auto issue = [&](int c, int s) {
        const __nv_bfloat16 *Ah, *Al, *Wh, *Wl;
        int lda, ldw, kc;
        if (c < nc0) { Ah = A0h; Al = A0l; Wh = W0h; Wl = W0l; lda = lda0; ldw = ldw0; kc = c << 5; }
        else         { Ah = A1h; Al = A1l; Wh = W1h; Wl = W1l; lda = lda1; ldw = ldw1; kc = (c - nc0) << 5; }
        const uint32_t sb = smb + (uint32_t)s * STAGEB;
        #pragma unroll
        for (int it = 0; it < 2; it++) {
            int idx = tid + it * 256;
            int row = idx >> 2, seg = idx & 3;
            uint32_t off = (uint32_t)(row * SSTR + seg * 8) * 2;
            size_t go = (size_t)(m0 + row) * lda + kc + seg * 8;
            CPA16(sb + off, Ah + go);
            CPA16(sb + ACH * 2 + off, Al + go);
        }
        #pragma unroll
        for (int it = 0; it < WIT; it++) {
            int idx = tid + it * 256;
            int row = idx >> 2, seg = idx & 3;
            uint32_t off = (uint32_t)(row * SSTR + seg * 8) * 2;
            size_t go = (size_t)(n0 + row) * ldw + kc + seg * 8;
            CPA16(sb + ACH * 4 + off, Wh + go);
            CPA16(sb + ACH * 4 + WCH * 2 + off, Wl + go);
        }
    };

    issue(0, 0);
    CPCOMMIT();

    for (int c = 0; c < NC; c++) {
        if (c + 1 < NC) {
            issue(c + 1, (c + 1) & 1);
            CPCOMMIT();
            CPWAIT1();
        } else {
            CPWAIT0();
        }
        __syncthreads();

        const uint32_t sb  = smb + (uint32_t)(c & 1) * STAGEB;
        const uint32_t bAh = sb;
        const uint32_t bAl = sb + ACH * 2;
        const uint32_t bWh = sb + ACH * 4;
        const uint32_t bWl = sb + ACH * 4 + WCH * 2;

        #pragma unroll
        for (int kk = 0; kk < 32; kk += 16) {
            uint32_t ah[2][4], al[2][4];
            #pragma unroll
            for (int mt = 0; mt < 2; mt++) {
                int row = wm * 32 + mt * 16 + (lane & 15);
                int col = kk + ((lane >> 4) << 3);
                uint32_t off = (uint32_t)(row * SSTR + col) * 2u;
                ldm4(ah[mt], bAh + off);
                ldm4(al[mt], bAl + off);
            }
            uint32_t bh[N16T][4], bl[N16T][4];
            #pragma unroll
            for (int t = 0; t < N16T; t++) {
                int row = wn * WN + t * 16 + (lane & 15);
                int col = kk + ((lane >> 4) << 3);
                uint32_t off = (uint32_t)(row * SSTR + col) * 2u;
                ldm4(bh[t], bWh + off);
                ldm4(bl[t], bWl + off);
            }
            #pragma unroll
            for (int mt = 0; mt < 2; mt++)
                #pragma unroll
                for (int nt = 0; nt < NT8; nt++) {
                    int t = nt >> 1, hs = nt & 1;
                    mma16816(acc[mt][nt], ah[mt], bh[t][hs], bh[t][2 + hs]);
                    mma16816(acc[mt][nt], al[mt], bh[t][hs], bh[t][2 + hs]);
                    mma16816(acc[mt][nt], ah[mt], bl[t][hs], bl[t][2 + hs]);
                }
        }
        __syncthreads();
    }

    // epilogue
    #pragma unroll
    for (int mt = 0; mt < 2; mt++) {
        int r0 = m0 + wm * 32 + mt * 16 + (lane >> 2);
        int r1 = r0 + 8;
        int ib0 = 0, ib1 = 0;
        if (EPI == 1) { ib0 = idxp[r0]; ib1 = idxp[r1]; }
        #pragma unroll
        for (int nt = 0; nt < NT8; nt++) {
            int cc = n0 + wn * WN + nt * 8 + ((lane & 3) << 1);
            if (cc < N) {
                #pragma unroll
                for (int p = 0; p < 2; p++) {
                    int r  = p ? r1 : r0;
                    int ib = p ? ib1 : ib0;
                    float x = acc[mt][nt][2 * p];
                    float y = acc[mt][nt][2 * p + 1];
                    if (EPI == 1) {
                        x += aux0[(size_t)ib * 1024 + cc];
                        y += aux0[(size_t)ib * 1024 + cc + 1];
                    } else if (bias) {
                        x += bias[cc];
                        y += bias[cc + 1];
                    }
                    if (ACT) { x = fmaxf(x, 0.f); y = fmaxf(y, 0.f); }
                    if (EPI == 2) {
                        x = tanhf(aux0[(size_t)r * 256 + cc] + x)     * aux1[(size_t)r * 512 + 256 + cc];
                        y = tanhf(aux0[(size_t)r * 256 + cc + 1] + y) * aux1[(size_t)r * 512 + 256 + cc + 1];
                    }
                    size_t o = (size_t)r * ldc + cc;
                    if (OUTM & 1)
                        *reinterpret_cast<float2*>(&C[o]) = make_float2(x, y);
                    if (OUTM & 2) {
                        __nv_bfloat16 xh, xl, yh, yl;
                        bsplit(x, xh, xl);
                        bsplit(y, yh, yl);
                        *reinterpret_cast<uint32_t*>(Ch + o) = pack2(xh, yh);
                        *reinterpret_cast<uint32_t*>(Cl + o) = pack2(xl, yl);
                    }
                }
            }
        }
    }
}

// ---------------------------------------------------------------------------
// Final heads
// ---------------------------------------------------------------------------
__global__ void k_heads(const float* __restrict__ pol2, const float* __restrict__ val2,
                        const float* __restrict__ w_p, const float* __restrict__ b_p,
                        const float* __restrict__ w_v, const float* __restrict__ b_v,
                        float* __restrict__ out_val, float* __restrict__ out_pol) {
    __shared__ float sp[64][65];
    __shared__ float sv[64][33];
    int r0 = blockIdx.x * 64;
    for (int i = threadIdx.x; i < 64 * 64; i += blockDim.x)
        sp[i >> 6][i & 63] = pol2[(size_t)r0 * 64 + i];
    for (int i = threadIdx.x; i < 64 * 32; i += blockDim.x)
        sv[i >> 5][i & 31] = val2[(size_t)r0 * 32 + i];
    __syncthreads();
    int t = threadIdx.x;
    if (t < 64) {
        int b = r0 + t;
        float p0 = b_p[0], p1 = b_p[1], p2 = b_p[2];
        #pragma unroll
        for (int k = 0; k < 64; k++) {
            float x = sp[t][k];
            p0 = fmaf(x, w_p[k], p0);
            p1 = fmaf(x, w_p[64 + k], p1);
            p2 = fmaf(x, w_p[128 + k], p2);
        }
        out_pol[(size_t)b * 3 + 0] = p0;
        out_pol[(size_t)b * 3 + 1] = p1;
        out_pol[(size_t)b * 3 + 2] = p2;
        float v = b_v[0];
        #pragma unroll
        for (int k = 0; k < 32; k++) v = fmaf(sv[t][k], w_v[k], v);
        out_val[b] = v;
    }
}

// ---------------------------------------------------------------------------
// host launcher
// ---------------------------------------------------------------------------
extern "C" void kernel_launch(void* const* d_in, const int* in_sizes, int n_in,
                              void* d_out, int out_size) {
    const float* img   = (const float*)d_in[0];
    const int*   idx   = (const int*)  d_in[1];
    const float* hx_in = (const float*)d_in[2];
    const float* cx_in = (const float*)d_in[3];
    const float* query = (const float*)d_in[4];
    const float* emb   = (const float*)d_in[5];
    const float* w_ta  = (const float*)d_in[6];
    const float* b_ta  = (const float*)d_in[7];
    const float* w_ih  = (const float*)d_in[8];
    const float* w_hh  = (const float*)d_in[9];
    const float* b_ih  = (const float*)d_in[10];
    const float* b_hh  = (const float*)d_in[11];
    const float* w_q   = (const float*)d_in[12];
    const float* b_q   = (const float*)d_in[13];
    const float* w_k   = (const float*)d_in[14];
    const float* b_k   = (const float*)d_in[15];
    const float* w_ba  = (const float*)d_in[16];
    const float* b_ba  = (const float*)d_in[17];
    const float* w_at  = (const float*)d_in[18];
    const float* b_at  = (const float*)d_in[19];
    const float* w_p1  = (const float*)d_in[20];
    const float* b_p1  = (const float*)d_in[21];
    const float* w_p2  = (const float*)d_in[22];
    const float* b_p2  = (const float*)d_in[23];
    const float* w_p   = (const float*)d_in[24];
    const float* b_p   = (const float*)d_in[25];
    const float* w_v1  = (const float*)d_in[26];
    const float* b_v1  = (const float*)d_in[27];
    const float* w_v2  = (const float*)d_in[28];
    const float* b_v2  = (const float*)d_in[29];
    const float* w_v   = (const float*)d_in[30];
    const float* b_v   = (const float*)d_in[31];

    const int B = in_sizes[0] / 256;  // 32768

    float* F = nullptr;
    cudaGetSymbolAddress((void**)&F, g_f32);
    __nv_bfloat16* BF = nullptr;
    cudaGetSymbolAddress((void**)&BF, g_bf);

    float* tab   = F + F_TAB;
    float* pre2  = F + F_PRE2;
    float* gates = F + F_GATES;
    float* mlpf  = F + F_MLP;
    float* qout  = F + F_QOUT;
    float* pol2  = F + F_POL2;
    float* val2  = F + F_VAL2;

    auto HI = [&](size_t o) { return BF + o; };
    auto LO = [&](size_t o) { return BF + o + B_HALF; };

    float* out   = (float*)d_out;
    float* o_val = out;
    float* o_pol = out + (size_t)B;
    float* o_hx  = out + (size_t)B * 4;
    float* o_cx  = o_hx + (size_t)B * 256;

    // dynamic smem sizes
    const int SM128 = (2 * 128 * 40 + 2 * 128 * 40) * 2 * 2;  // 81920
    const int SM64  = (2 * 128 * 40 + 2 * 64 * 40) * 2 * 2;   // 61440
    cudaFuncSetAttribute(mma_gemm<128, 0, 1, 1>, cudaFuncAttributeMaxDynamicSharedMemorySize, SM128);
    cudaFuncSetAttribute(mma_gemm<128, 1, 0, 3>, cudaFuncAttributeMaxDynamicSharedMemorySize, SM128);
    cudaFuncSetAttribute(mma_gemm<128, 1, 0, 1>, cudaFuncAttributeMaxDynamicSharedMemorySize, SM128);
    cudaFuncSetAttribute(mma_gemm<128, 1, 2, 2>, cudaFuncAttributeMaxDynamicSharedMemorySize, SM128);
    cudaFuncSetAttribute(mma_gemm<128, 1, 0, 2>, cudaFuncAttributeMaxDynamicSharedMemorySize, SM128);
    cudaFuncSetAttribute(mma_gemm<64, 1, 0, 1>,  cudaFuncAttributeMaxDynamicSharedMemorySize, SM64);
    cudaFuncSetAttribute(mma_gemm<64, 1, 0, 2>,  cudaFuncAttributeMaxDynamicSharedMemorySize, SM64);

    // K0: tables
    k0_tables<<<1, 1024>>>(emb, w_ta, b_ta, w_ih, b_ih, b_hh, tab, pre2);

    // weight splits (pad w_v2 to 64 rows)
    auto wsplit = [&](const float* src, int srcld, int cols, int rows, int padrows, size_t off) {
        int total = padrows * cols;
        k_wsplit<<<(total + 255) / 256, 256>>>(src, srcld, cols, rows, HI(off), LO(off), total);
    };
    wsplit(w_ih, 512, 256, 1024, 1024, B_WIH);   // compact cols 0:256
    wsplit(w_hh, 256, 256, 1024, 1024, B_WHH);
    wsplit(w_ba, 512, 512, 512, 512, B_WBA);
    wsplit(w_q,  256, 256, 256, 256, B_WQ);
    wsplit(w_k,  256, 256, 256, 256, B_WK);
    wsplit(w_at, 512, 512, 256, 256, B_WAT);
    wsplit(w_p1, 256, 256, 128, 128, B_WP1);
    wsplit(w_p2, 128, 128, 64, 64, B_WP2);
    wsplit(w_v1, 256, 256, 64, 64, B_WV1);
    wsplit(w_v2, 64, 64, 32, 64, B_WV2);

    // activation splits
    k_asplit<<<(B * 64 + 255) / 256, 256>>>((const float4*)hx_in, HI(B_HXI), LO(B_HXI), B * 64);
    k_asplit<<<(B * 64 + 255) / 256, 256>>>((const float4*)query, HI(B_QRY), LO(B_QRY), B * 64);

    // K1: gated_fusion -> bf16
    k_fusion<<<(B * 64 + 255) / 256, 256>>>((const float4*)img, idx, tab, HI(B_FUS), LO(B_FUS), B * 64);

    // K2: gates = fus @ w_ih[:,:256]^T + hx @ w_hh^T + pre2[idx]   (fp32 out)
    mma_gemm<128, 0, 1, 1><<<dim3(8, B / 128), 256, SM128>>>(
        1024,
        HI(B_FUS), LO(B_FUS), 256, HI(B_WIH), LO(B_WIH), 256, 256,
        HI(B_HXI), LO(B_HXI), 256, HI(B_WHH), LO(B_WHH), 256, 256,
        nullptr, pre2, nullptr, idx, gates, nullptr, nullptr, 1024);

    // K3: LSTM -> o_hx/o_cx fp32 + hx bf16
    k_lstm<<<(B * 64 + 255) / 256, 256>>>(gates, cx_in, o_hx, o_cx, HI(B_HXO), LO(B_HXO), B * 64);

    // K5: qout = relu(query @ w_q^T + b_q)   (fp32 out)
    mma_gemm<128, 1, 0, 1><<<dim3(2, B / 128), 256, SM128>>>(
        256,
        HI(B_QRY), LO(B_QRY), 256, HI(B_WQ), LO(B_WQ), 256, 256,
        nullptr, nullptr, 0, nullptr, nullptr, 0, 0,
        b_q, nullptr, nullptr, nullptr, qout, nullptr, nullptr, 256);

    // K4: mlp = relu([fus|hx] @ w_ba^T + b_ba)   (fp32 + bf16 out)
    mma_gemm<128, 1, 0, 3><<<dim3(4, B / 128), 256, SM128>>>(
        512,
        HI(B_FUS), LO(B_FUS), 256, HI(B_WBA), LO(B_WBA), 512, 256,
        HI(B_HXO), LO(B_HXO), 256, HI(B_WBA) + 256, LO(B_WBA) + 256, 512, 256,
        b_ba, nullptr, nullptr, nullptr, mlpf, HI(B_MLP), LO(B_MLP), 512);

    // K6: avec = tanh(qout + relu(key @ w_k^T + b_k)) * val   (bf16 out)
    mma_gemm<128, 1, 2, 2><<<dim3(2, B / 128), 256, SM128>>>(
        256,
        HI(B_MLP), LO(B_MLP), 512, HI(B_WK), LO(B_WK), 256, 256,
        nullptr, nullptr, 0, nullptr, nullptr, 0, 0,
        b_k, qout, mlpf, nullptr, nullptr, HI(B_AVEC), LO(B_AVEC), 256);

    // K7: attnw = relu([avec|hx] @ w_at^T + b_at)   (bf16 out)
    mma_gemm<128, 1, 0, 2><<<dim3(2, B / 128), 256, SM128>>>(
        256,
        HI(B_AVEC), LO(B_AVEC), 256, HI(B_WAT), LO(B_WAT), 512, 256,
        HI(B_HXO), LO(B_HXO), 256, HI(B_WAT) + 256, LO(B_WAT) + 256, 512, 256,
        b_at, nullptr, nullptr, nullptr, nullptr, HI(B_ATT), LO(B_ATT), 256);

    // K8: pol1 = relu(attnw @ w_p1^T + b_p1)   (bf16 out)
    mma_gemm<128, 1, 0, 2><<<dim3(1, B / 128), 256, SM128>>>(
        128,
        HI(B_ATT), LO(B_ATT), 256, HI(B_WP1), LO(B_WP1), 256, 256,
        nullptr, nullptr, 0, nullptr, nullptr, 0, 0,
        b_p1, nullptr, nullptr, nullptr, nullptr, HI(B_POL1), LO(B_POL1), 128);

    // K9: pol2 = relu(pol1 @ w_p2^T + b_p2)   (fp32 out)
    mma_gemm<64, 1, 0, 1><<<dim3(1, B / 128), 256, SM64>>>(
        64,
        HI(B_POL1), LO(B_POL1), 128, HI(B_WP2), LO(B_WP2), 128, 128,
        nullptr, nullptr, 0, nullptr, nullptr, 0, 0,
        b_p2, nullptr, nullptr, nullptr, pol2, nullptr, nullptr, 64);

    // K10: val1 = relu(attnw @ w_v1^T + b_v1)   (bf16 out)
    mma_gemm<64, 1, 0, 2><<<dim3(1, B / 128), 256, SM64>>>(
        64,
        HI(B_ATT), LO(B_ATT), 256, HI(B_WV1), LO(B_WV1), 256, 256,
        nullptr, nullptr, 0, nullptr, nullptr, 0, 0,
        b_v1, nullptr, nullptr, nullptr, nullptr, HI(B_VAL1), LO(B_VAL1), 64);

    // K11: val2 = relu(val1 @ w_v2^T + b_v2)   (fp32 out; W padded to 64 rows; ldc=32!)
    mma_gemm<64, 1, 0, 1><<<dim3(1, B / 128), 256, SM64>>>(
        32,
        HI(B_VAL1), LO(B_VAL1), 64, HI(B_WV2), LO(B_WV2), 64, 64,
        nullptr, nullptr, 0, nullptr, nullptr, 0, 0,
        b_v2, nullptr, nullptr, nullptr, val2, nullptr, nullptr, 32);

    // K12: heads
    k_heads<<<B / 64, 256>>>(pol2, val2, w_p, b_p, w_v, b_v, o_val, o_pol);
}